// round 6
// baseline (speedup 1.0000x reference)
#include <cuda_runtime.h>
#include <cuda_bf16.h>
#include <math.h>
#include <stdint.h>

// Problem constants: N=100000, D=128, C=1024, NUM_NODES=1e6.
#define MAX_N     100000
#define MAX_NODES 1000000
#define NCB       8            // C / BN column blocks

// Device scratch (no allocs allowed). NO 64-bit atomics (sm_103a trap).
__device__ unsigned long long g_cand[(size_t)(MAX_N + 128) * NCB];
__device__ int   g_winner[MAX_NODES];
__device__ float g_rn[MAX_N];
__device__ float g_cn[2048];

// ---------------------------------------------------------------------------
__global__ void clear_kernel(int m) {
    int i = blockIdx.x * blockDim.x + threadIdx.x;
    if (i < m) g_winner[i] = -1;
}

__global__ void rownorm_kernel(const float* __restrict__ X, int n, int D, int is_col) {
    int warp = (blockIdx.x * blockDim.x + threadIdx.x) >> 5;
    int lane = threadIdx.x & 31;
    if (warp >= n) return;
    const float* row = X + (size_t)warp * D;
    float s = 0.f;
    for (int k = lane; k < D; k += 32) { float v = row[k]; s += v * v; }
    #pragma unroll
    for (int o = 16; o; o >>= 1) s += __shfl_xor_sync(0xFFFFFFFFu, s, o);
    if (lane == 0) { if (is_col) g_cn[warp] = s; else g_rn[warp] = s; }
}

__global__ void copy_tables_kernel(const int* __restrict__ node_cell,
                                   const float* __restrict__ node_time,
                                   float* __restrict__ out_ncell,
                                   float* __restrict__ out_ntime, int m) {
    int j = blockIdx.x * blockDim.x + threadIdx.x;
    if (j < m) {
        if (out_ncell) out_ncell[j] = (float)node_cell[j];
        if (out_ntime) out_ntime[j] = node_time[j];
    }
}

__global__ void winner_kernel(const int* __restrict__ nodes, int n, int m) {
    int i = blockIdx.x * blockDim.x + threadIdx.x;
    if (i >= n) return;
    int nd = nodes[i];
    if (nd >= 0 && nd < m) atomicMax(&g_winner[nd], i);
}

// ---------------------------------------------------------------------------
// Tensor-core distance GEMM: 3xTF32 (hh + hl + lh) == fp32 accuracy.
// hi/lo split hoisted to smem-store time; main loop is pure LDS + HMMA.
#define BM 128
#define BN 128
#define BK 32
#define SROW (BK + 4)          // 36-float row stride: 16B-aligned, conflict-free frags

#define SMEM_TILE (BM * SROW)                       // floats per tile
#define SMEM_BYTES (4 * SMEM_TILE * 4 + BM * 4 * 8) // 4 tiles + best_sh

__device__ __forceinline__ void split_tf32(float x, uint32_t& hi, uint32_t& lo) {
    uint32_t xb = __float_as_uint(x);
    uint32_t h  = (xb + 0x1000u) & 0xFFFFE000u;   // round-to-nearest tf32
    hi = h;
    lo = __float_as_uint(x - __uint_as_float(h));
}

__device__ __forceinline__ void mma_tf32(float* c, const uint32_t* a, const uint32_t* b) {
    asm volatile(
        "mma.sync.aligned.m16n8k8.row.col.f32.tf32.tf32.f32 "
        "{%0,%1,%2,%3}, {%4,%5,%6,%7}, {%8,%9}, {%0,%1,%2,%3};\n"
        : "+f"(c[0]), "+f"(c[1]), "+f"(c[2]), "+f"(c[3])
        : "r"(a[0]), "r"(a[1]), "r"(a[2]), "r"(a[3]), "r"(b[0]), "r"(b[1]));
}

__global__ __launch_bounds__(256)
void gemm_dist_tc(const float* __restrict__ A,   // [N, 128]
                  const float* __restrict__ B,   // [1024, 128]
                  float* __restrict__ out,       // [N, 1024] (may be null)
                  int N, int C, int D) {
    extern __shared__ float smem[];
    float* As_hi = smem;
    float* As_lo = As_hi + SMEM_TILE;
    float* Bs_hi = As_lo + SMEM_TILE;
    float* Bs_lo = Bs_hi + SMEM_TILE;
    unsigned long long* best_sh = (unsigned long long*)(Bs_lo + SMEM_TILE); // [BM][4]

    const int tid   = threadIdx.x;
    const int lane  = tid & 31;
    const int warp  = tid >> 5;
    const int warpM = warp >> 2;       // 0..1
    const int warpN = warp & 3;        // 0..3
    const int brow  = blockIdx.y * BM;
    const int bcol  = blockIdx.x * BN;
    const int g     = lane >> 2;       // groupID 0..7
    const int q     = lane & 3;        // quad lane 0..3

    float acc[4][4][4];                // [mtile][ntile][reg]
    #pragma unroll
    for (int mt = 0; mt < 4; mt++)
        #pragma unroll
        for (int nt = 0; nt < 4; nt++)
            #pragma unroll
            for (int r = 0; r < 4; r++) acc[mt][nt][r] = 0.f;

    // Loader mapping: 256 threads, each 4 float4 per tile per matrix.
    const int lrow = tid >> 3;          // 0..31
    const int lk4  = (tid & 7) * 4;     // 0..28

    for (int kc = 0; kc < 4; kc++) {
        const int k0 = kc * BK;
        float4 av[4], bv[4];
        #pragma unroll
        for (int i = 0; i < 4; i++) {
            int ar = min(brow + lrow + i * 32, N - 1);
            av[i] = *(const float4*)(A + (size_t)ar * D + k0 + lk4);
            bv[i] = *(const float4*)(B + (size_t)(bcol + lrow + i * 32) * D + k0 + lk4);
        }
        __syncthreads();
        #pragma unroll
        for (int i = 0; i < 4; i++) {
            int base = (lrow + i * 32) * SROW + lk4;
            float4 h4, l4;
            uint32_t h, l;
            split_tf32(av[i].x, h, l); h4.x = __uint_as_float(h); l4.x = __uint_as_float(l);
            split_tf32(av[i].y, h, l); h4.y = __uint_as_float(h); l4.y = __uint_as_float(l);
            split_tf32(av[i].z, h, l); h4.z = __uint_as_float(h); l4.z = __uint_as_float(l);
            split_tf32(av[i].w, h, l); h4.w = __uint_as_float(h); l4.w = __uint_as_float(l);
            *(float4*)&As_hi[base] = h4;
            *(float4*)&As_lo[base] = l4;
            split_tf32(bv[i].x, h, l); h4.x = __uint_as_float(h); l4.x = __uint_as_float(l);
            split_tf32(bv[i].y, h, l); h4.y = __uint_as_float(h); l4.y = __uint_as_float(l);
            split_tf32(bv[i].z, h, l); h4.z = __uint_as_float(h); l4.z = __uint_as_float(l);
            split_tf32(bv[i].w, h, l); h4.w = __uint_as_float(h); l4.w = __uint_as_float(l);
            *(float4*)&Bs_hi[base] = h4;
            *(float4*)&Bs_lo[base] = l4;
        }
        __syncthreads();

        #pragma unroll
        for (int kk = 0; kk < 4; kk++) {
            const int kb = kk * 8;
            uint32_t ah[4][4], al[4][4];
            #pragma unroll
            for (int mt = 0; mt < 4; mt++) {
                int r0 = (warpM * 64 + mt * 16 + g) * SROW;
                int c0 = kb + q;
                ah[mt][0] = __float_as_uint(As_hi[r0 + c0]);
                ah[mt][1] = __float_as_uint(As_hi[r0 + 8 * SROW + c0]);
                ah[mt][2] = __float_as_uint(As_hi[r0 + c0 + 4]);
                ah[mt][3] = __float_as_uint(As_hi[r0 + 8 * SROW + c0 + 4]);
                al[mt][0] = __float_as_uint(As_lo[r0 + c0]);
                al[mt][1] = __float_as_uint(As_lo[r0 + 8 * SROW + c0]);
                al[mt][2] = __float_as_uint(As_lo[r0 + c0 + 4]);
                al[mt][3] = __float_as_uint(As_lo[r0 + 8 * SROW + c0 + 4]);
            }
            #pragma unroll
            for (int nt = 0; nt < 4; nt++) {
                int n0 = (warpN * 32 + nt * 8 + g) * SROW;
                uint32_t bh[2], bl[2];
                bh[0] = __float_as_uint(Bs_hi[n0 + kb + q]);
                bh[1] = __float_as_uint(Bs_hi[n0 + kb + q + 4]);
                bl[0] = __float_as_uint(Bs_lo[n0 + kb + q]);
                bl[1] = __float_as_uint(Bs_lo[n0 + kb + q + 4]);
                #pragma unroll
                for (int mt = 0; mt < 4; mt++) {
                    mma_tf32(acc[mt][nt], ah[mt], bh);
                    mma_tf32(acc[mt][nt], ah[mt], bl);
                    mma_tf32(acc[mt][nt], al[mt], bh);
                }
            }
        }
    }

    // Epilogue: distances + per-row argmin keys.
    float cn0[4], cn1[4];
    #pragma unroll
    for (int nt = 0; nt < 4; nt++) {
        int col = bcol + warpN * 32 + nt * 8 + q * 2;
        cn0[nt] = g_cn[col];
        cn1[nt] = g_cn[col + 1];
    }

    #pragma unroll
    for (int mt = 0; mt < 4; mt++) {
        #pragma unroll
        for (int half = 0; half < 2; half++) {
            int rloc = warpM * 64 + mt * 16 + g + half * 8;
            int grow = brow + rloc;
            bool rowok = (grow < N);
            float rn = rowok ? g_rn[grow] : 0.f;
            unsigned long long best = ~0ull;
            #pragma unroll
            for (int nt = 0; nt < 4; nt++) {
                int col = bcol + warpN * 32 + nt * 8 + q * 2;
                float d0 = sqrtf(fmaxf(rn + cn0[nt] - 2.0f * acc[mt][nt][half * 2 + 0], 0.f));
                float d1 = sqrtf(fmaxf(rn + cn1[nt] - 2.0f * acc[mt][nt][half * 2 + 1], 0.f));
                unsigned long long k0 =
                    ((unsigned long long)__float_as_uint(d0) << 32) | (unsigned)col;
                unsigned long long k1 =
                    ((unsigned long long)__float_as_uint(d1) << 32) | (unsigned)(col + 1);
                best = (k0 < best) ? k0 : best;
                best = (k1 < best) ? k1 : best;
                if (rowok && out) {
                    float2 dv = make_float2(d0, d1);
                    *(float2*)(out + (size_t)grow * C + col) = dv;
                }
            }
            #pragma unroll
            for (int o = 1; o <= 2; o <<= 1) {
                unsigned long long other = __shfl_xor_sync(0xFFFFFFFFu, best, o);
                best = (other < best) ? other : best;
            }
            if (q == 0) best_sh[rloc * 4 + warpN] = best;
        }
    }
    __syncthreads();

    if (tid < BM) {
        int grow = brow + tid;
        if (grow < N) {
            unsigned long long best = best_sh[tid * 4];
            #pragma unroll
            for (int j = 1; j < 4; j++) {
                unsigned long long k = best_sh[tid * 4 + j];
                best = (k < best) ? k : best;
            }
            g_cand[(size_t)grow * NCB + blockIdx.x] = best;
        }
    }
}

// ---------------------------------------------------------------------------
__global__ void scatter_kernel(const int* __restrict__ nodes,
                               const float* __restrict__ times,
                               float* __restrict__ out_cells,
                               float* __restrict__ out_ncell,
                               float* __restrict__ out_ntime, int n, int m) {
    int i = blockIdx.x * blockDim.x + threadIdx.x;
    if (i >= n) return;
    const unsigned long long* cand = &g_cand[(size_t)i * NCB];
    unsigned long long best = cand[0];
    #pragma unroll
    for (int cb = 1; cb < NCB; cb++) {
        unsigned long long k = cand[cb];
        best = (k < best) ? k : best;
    }
    int cell = (int)(unsigned)(best & 0xFFFFFFFFull);
    if (out_cells) out_cells[i] = (float)cell;
    int nd = nodes[i];
    if (nd >= 0 && nd < m && g_winner[nd] == i) {
        if (out_ncell) out_ncell[nd] = (float)cell;
        if (out_ntime) out_ntime[nd] = times[i];
    }
}

// ---------------------------------------------------------------------------
extern "C" void kernel_launch(void* const* d_in, const int* in_sizes, int n_in,
                              void* d_out, int out_size) {
    const float* emb       = (const float*)d_in[0];   // [N, D]
    const float* mmap      = (const float*)d_in[1];   // [C, D]
    const int*   nodes     = (const int*)d_in[2];     // [N]
    const float* times     = (const float*)d_in[3];   // [N]
    const int*   node_cell = (const int*)d_in[4];     // [NUM_NODES]
    const float* node_time = (const float*)d_in[5];   // [NUM_NODES]

    const int D = 128;
    const int N = in_sizes[0] / D;       // 100000
    const int C = in_sizes[1] / D;       // 1024
    const int M = in_sizes[4];           // 1000000

    size_t have = (size_t)out_size;
    size_t nc = (size_t)N * C;
    float* base = (float*)d_out;
    float* out_dist  = (have >= nc) ? base : nullptr;
    float* out_cells = (have >= nc + (size_t)N) ? base + nc : nullptr;
    float* out_ncell = (have >= nc + N + (size_t)M) ? base + nc + N : nullptr;
    float* out_ntime = (have >= nc + N + 2ull * M) ? base + nc + N + M : nullptr;

    clear_kernel<<<(M + 255) / 256, 256>>>(M);
    rownorm_kernel<<<(N * 32 + 255) / 256, 256>>>(emb, N, D, 0);
    rownorm_kernel<<<(C * 32 + 255) / 256, 256>>>(mmap, C, D, 1);
    if (out_ncell || out_ntime)
        copy_tables_kernel<<<(M + 255) / 256, 256>>>(node_cell, node_time,
                                                     out_ncell, out_ntime, M);
    winner_kernel<<<(N + 255) / 256, 256>>>(nodes, N, M);
    {
        cudaFuncSetAttribute(gemm_dist_tc,
                             cudaFuncAttributeMaxDynamicSharedMemorySize, SMEM_BYTES);
        dim3 grid(C / BN, (N + BM - 1) / BM);
        gemm_dist_tc<<<grid, 256, SMEM_BYTES>>>(emb, mmap, out_dist, N, C, D);
    }
    scatter_kernel<<<(N + 255) / 256, 256>>>(nodes, times, out_cells,
                                             out_ncell, out_ntime, N, M);
}

// round 8
// speedup vs baseline: 1.2222x; 1.2222x over previous
#include <cuda_runtime.h>
#include <cuda_bf16.h>
#include <math.h>
#include <stdint.h>

// Problem constants: N=100000, D=128, C=1024, NUM_NODES=1e6.
#define MAX_N     100000
#define MAX_NODES 1000000
#define NCB       8            // C / BN column blocks

// Device scratch (no allocs allowed). NO 64-bit atomics (sm_103a trap).
__device__ unsigned long long g_cand[(size_t)(MAX_N + 128) * NCB];
__device__ int   g_winner[MAX_NODES];
__device__ float g_rn[MAX_N];
__device__ float g_cn[2048];

// ---------------------------------------------------------------------------
__global__ void clear_kernel(int m) {
    int i = blockIdx.x * blockDim.x + threadIdx.x;
    if (i < m) g_winner[i] = -1;
}

__global__ void rownorm_kernel(const float* __restrict__ X, int n, int D, int is_col) {
    int warp = (blockIdx.x * blockDim.x + threadIdx.x) >> 5;
    int lane = threadIdx.x & 31;
    if (warp >= n) return;
    const float* row = X + (size_t)warp * D;
    float s = 0.f;
    for (int k = lane; k < D; k += 32) { float v = row[k]; s += v * v; }
    #pragma unroll
    for (int o = 16; o; o >>= 1) s += __shfl_xor_sync(0xFFFFFFFFu, s, o);
    if (lane == 0) { if (is_col) g_cn[warp] = s; else g_rn[warp] = s; }
}

__global__ void copy_tables_kernel(const int* __restrict__ node_cell,
                                   const float* __restrict__ node_time,
                                   float* __restrict__ out_ncell,
                                   float* __restrict__ out_ntime, int m) {
    int j = blockIdx.x * blockDim.x + threadIdx.x;
    if (j < m) {
        if (out_ncell) out_ncell[j] = (float)node_cell[j];
        if (out_ntime) out_ntime[j] = node_time[j];
    }
}

__global__ void winner_kernel(const int* __restrict__ nodes, int n, int m) {
    int i = blockIdx.x * blockDim.x + threadIdx.x;
    if (i >= n) return;
    int nd = nodes[i];
    if (nd >= 0 && nd < m) atomicMax(&g_winner[nd], i);
}

// ---------------------------------------------------------------------------
// Tensor-core distance GEMM: 3xTF32 (hh + hl + lh) == fp32 accuracy.
// hi/lo split hoisted to smem store; BK=16 keeps smem at 45KB -> 2 CTAs/SM.
#define BM 128
#define BN 128
#define BK 16
#define SROW (BK + 4)          // 20-float stride: 16B-aligned rows, conflict-free

__device__ __forceinline__ void split_tf32(float x, uint32_t& hi, uint32_t& lo) {
    uint32_t xb = __float_as_uint(x);
    uint32_t h  = (xb + 0x1000u) & 0xFFFFE000u;   // round-to-nearest tf32
    hi = h;
    lo = __float_as_uint(x - __uint_as_float(h));
}

__device__ __forceinline__ void mma_tf32(float* c, const uint32_t* a, const uint32_t* b) {
    asm volatile(
        "mma.sync.aligned.m16n8k8.row.col.f32.tf32.tf32.f32 "
        "{%0,%1,%2,%3}, {%4,%5,%6,%7}, {%8,%9}, {%0,%1,%2,%3};\n"
        : "+f"(c[0]), "+f"(c[1]), "+f"(c[2]), "+f"(c[3])
        : "r"(a[0]), "r"(a[1]), "r"(a[2]), "r"(a[3]), "r"(b[0]), "r"(b[1]));
}

__global__ __launch_bounds__(256, 2)
void gemm_dist_tc(const float* __restrict__ A,   // [N, 128]
                  const float* __restrict__ B,   // [1024, 128]
                  float* __restrict__ out,       // [N, 1024] (may be null)
                  int N, int C, int D) {
    __shared__ float As_hi[BM][SROW];
    __shared__ float As_lo[BM][SROW];
    __shared__ float Bs_hi[BN][SROW];
    __shared__ float Bs_lo[BN][SROW];
    __shared__ unsigned long long best_sh[BM][4];

    const int tid   = threadIdx.x;
    const int lane  = tid & 31;
    const int warp  = tid >> 5;
    const int warpM = warp >> 2;       // 0..1
    const int warpN = warp & 3;        // 0..3
    const int brow  = blockIdx.y * BM;
    const int bcol  = blockIdx.x * BN;
    const int g     = lane >> 2;       // groupID 0..7
    const int q     = lane & 3;        // quad lane 0..3

    float acc[4][4][4];                // [mtile][ntile][reg]
    #pragma unroll
    for (int mt = 0; mt < 4; mt++)
        #pragma unroll
        for (int nt = 0; nt < 4; nt++)
            #pragma unroll
            for (int r = 0; r < 4; r++) acc[mt][nt][r] = 0.f;

    // Loader mapping: 256 threads -> 128 rows x 2 float4 (16 cols) per matrix.
    const int lrow = tid >> 1;          // 0..127
    const int lc   = (tid & 1) * 8;     // 0 or 8
    const int ga   = min(brow + lrow, N - 1);
    const int gb   = bcol + lrow;

    for (int kc = 0; kc < 8; kc++) {
        const int k0 = kc * BK;
        float4 av0 = *(const float4*)(A + (size_t)ga * D + k0 + lc);
        float4 av1 = *(const float4*)(A + (size_t)ga * D + k0 + lc + 4);
        float4 bv0 = *(const float4*)(B + (size_t)gb * D + k0 + lc);
        float4 bv1 = *(const float4*)(B + (size_t)gb * D + k0 + lc + 4);
        __syncthreads();
        {
            float4 h4, l4; uint32_t h, l;
            split_tf32(av0.x, h, l); h4.x = __uint_as_float(h); l4.x = __uint_as_float(l);
            split_tf32(av0.y, h, l); h4.y = __uint_as_float(h); l4.y = __uint_as_float(l);
            split_tf32(av0.z, h, l); h4.z = __uint_as_float(h); l4.z = __uint_as_float(l);
            split_tf32(av0.w, h, l); h4.w = __uint_as_float(h); l4.w = __uint_as_float(l);
            *(float4*)&As_hi[lrow][lc] = h4; *(float4*)&As_lo[lrow][lc] = l4;
            split_tf32(av1.x, h, l); h4.x = __uint_as_float(h); l4.x = __uint_as_float(l);
            split_tf32(av1.y, h, l); h4.y = __uint_as_float(h); l4.y = __uint_as_float(l);
            split_tf32(av1.z, h, l); h4.z = __uint_as_float(h); l4.z = __uint_as_float(l);
            split_tf32(av1.w, h, l); h4.w = __uint_as_float(h); l4.w = __uint_as_float(l);
            *(float4*)&As_hi[lrow][lc + 4] = h4; *(float4*)&As_lo[lrow][lc + 4] = l4;
            split_tf32(bv0.x, h, l); h4.x = __uint_as_float(h); l4.x = __uint_as_float(l);
            split_tf32(bv0.y, h, l); h4.y = __uint_as_float(h); l4.y = __uint_as_float(l);
            split_tf32(bv0.z, h, l); h4.z = __uint_as_float(h); l4.z = __uint_as_float(l);
            split_tf32(bv0.w, h, l); h4.w = __uint_as_float(h); l4.w = __uint_as_float(l);
            *(float4*)&Bs_hi[lrow][lc] = h4; *(float4*)&Bs_lo[lrow][lc] = l4;
            split_tf32(bv1.x, h, l); h4.x = __uint_as_float(h); l4.x = __uint_as_float(l);
            split_tf32(bv1.y, h, l); h4.y = __uint_as_float(h); l4.y = __uint_as_float(l);
            split_tf32(bv1.z, h, l); h4.z = __uint_as_float(h); l4.z = __uint_as_float(l);
            split_tf32(bv1.w, h, l); h4.w = __uint_as_float(h); l4.w = __uint_as_float(l);
            *(float4*)&Bs_hi[lrow][lc + 4] = h4; *(float4*)&Bs_lo[lrow][lc + 4] = l4;
        }
        __syncthreads();

        #pragma unroll
        for (int kk = 0; kk < 2; kk++) {
            const int kb = kk * 8;
            const int c0 = kb + q;
            uint32_t ah[4][4], al[4][4];
            #pragma unroll
            for (int mt = 0; mt < 4; mt++) {
                int r0 = warpM * 64 + mt * 16 + g;
                ah[mt][0] = __float_as_uint(As_hi[r0    ][c0    ]);
                ah[mt][1] = __float_as_uint(As_hi[r0 + 8][c0    ]);
                ah[mt][2] = __float_as_uint(As_hi[r0    ][c0 + 4]);
                ah[mt][3] = __float_as_uint(As_hi[r0 + 8][c0 + 4]);
                al[mt][0] = __float_as_uint(As_lo[r0    ][c0    ]);
                al[mt][1] = __float_as_uint(As_lo[r0 + 8][c0    ]);
                al[mt][2] = __float_as_uint(As_lo[r0    ][c0 + 4]);
                al[mt][3] = __float_as_uint(As_lo[r0 + 8][c0 + 4]);
            }
            #pragma unroll
            for (int nt = 0; nt < 4; nt++) {
                int n0 = warpN * 32 + nt * 8 + g;
                uint32_t bh[2], bl[2];
                bh[0] = __float_as_uint(Bs_hi[n0][c0]);
                bh[1] = __float_as_uint(Bs_hi[n0][c0 + 4]);
                bl[0] = __float_as_uint(Bs_lo[n0][c0]);
                bl[1] = __float_as_uint(Bs_lo[n0][c0 + 4]);
                #pragma unroll
                for (int mt = 0; mt < 4; mt++) {
                    mma_tf32(acc[mt][nt], ah[mt], bh);
                    mma_tf32(acc[mt][nt], ah[mt], bl);
                    mma_tf32(acc[mt][nt], al[mt], bh);
                }
            }
        }
    }

    // Epilogue: distances + per-row argmin keys.
    float cn0[4], cn1[4];
    #pragma unroll
    for (int nt = 0; nt < 4; nt++) {
        int col = bcol + warpN * 32 + nt * 8 + q * 2;
        cn0[nt] = g_cn[col];
        cn1[nt] = g_cn[col + 1];
    }

    #pragma unroll
    for (int mt = 0; mt < 4; mt++) {
        #pragma unroll
        for (int half = 0; half < 2; half++) {
            int rloc = warpM * 64 + mt * 16 + g + half * 8;
            int grow = brow + rloc;
            bool rowok = (grow < N);
            float rn = rowok ? g_rn[grow] : 0.f;
            unsigned long long best = ~0ull;
            #pragma unroll
            for (int nt = 0; nt < 4; nt++) {
                int col = bcol + warpN * 32 + nt * 8 + q * 2;
                float d0 = sqrtf(fmaxf(rn + cn0[nt] - 2.0f * acc[mt][nt][half * 2 + 0], 0.f));
                float d1 = sqrtf(fmaxf(rn + cn1[nt] - 2.0f * acc[mt][nt][half * 2 + 1], 0.f));
                unsigned long long k0 =
                    ((unsigned long long)__float_as_uint(d0) << 32) | (unsigned)col;
                unsigned long long k1 =
                    ((unsigned long long)__float_as_uint(d1) << 32) | (unsigned)(col + 1);
                best = (k0 < best) ? k0 : best;
                best = (k1 < best) ? k1 : best;
                if (rowok && out) {
                    float2 dv = make_float2(d0, d1);
                    *(float2*)(out + (size_t)grow * C + col) = dv;
                }
            }
            #pragma unroll
            for (int o = 1; o <= 2; o <<= 1) {
                unsigned long long other = __shfl_xor_sync(0xFFFFFFFFu, best, o);
                best = (other < best) ? other : best;
            }
            if (q == 0) best_sh[rloc][warpN] = best;
        }
    }
    __syncthreads();

    if (tid < BM) {
        int grow = brow + tid;
        if (grow < N) {
            unsigned long long best = best_sh[tid][0];
            #pragma unroll
            for (int j = 1; j < 4; j++) {
                unsigned long long k = best_sh[tid][j];
                best = (k < best) ? k : best;
            }
            g_cand[(size_t)grow * NCB + blockIdx.x] = best;
        }
    }
}

// ---------------------------------------------------------------------------
__global__ void scatter_kernel(const int* __restrict__ nodes,
                               const float* __restrict__ times,
                               float* __restrict__ out_cells,
                               float* __restrict__ out_ncell,
                               float* __restrict__ out_ntime, int n, int m) {
    int i = blockIdx.x * blockDim.x + threadIdx.x;
    if (i >= n) return;
    const unsigned long long* cand = &g_cand[(size_t)i * NCB];
    unsigned long long best = cand[0];
    #pragma unroll
    for (int cb = 1; cb < NCB; cb++) {
        unsigned long long k = cand[cb];
        best = (k < best) ? k : best;
    }
    int cell = (int)(unsigned)(best & 0xFFFFFFFFull);
    if (out_cells) out_cells[i] = (float)cell;
    int nd = nodes[i];
    if (nd >= 0 && nd < m && g_winner[nd] == i) {
        if (out_ncell) out_ncell[nd] = (float)cell;
        if (out_ntime) out_ntime[nd] = times[i];
    }
}

// ---------------------------------------------------------------------------
extern "C" void kernel_launch(void* const* d_in, const int* in_sizes, int n_in,
                              void* d_out, int out_size) {
    const float* emb       = (const float*)d_in[0];   // [N, D]
    const float* mmap      = (const float*)d_in[1];   // [C, D]
    const int*   nodes     = (const int*)d_in[2];     // [N]
    const float* times     = (const float*)d_in[3];   // [N]
    const int*   node_cell = (const int*)d_in[4];     // [NUM_NODES]
    const float* node_time = (const float*)d_in[5];   // [NUM_NODES]

    const int D = 128;
    const int N = in_sizes[0] / D;       // 100000
    const int C = in_sizes[1] / D;       // 1024
    const int M = in_sizes[4];           // 1000000

    size_t have = (size_t)out_size;
    size_t nc = (size_t)N * C;
    float* base = (float*)d_out;
    float* out_dist  = (have >= nc) ? base : nullptr;
    float* out_cells = (have >= nc + (size_t)N) ? base + nc : nullptr;
    float* out_ncell = (have >= nc + N + (size_t)M) ? base + nc + N : nullptr;
    float* out_ntime = (have >= nc + N + 2ull * M) ? base + nc + N + M : nullptr;

    clear_kernel<<<(M + 255) / 256, 256>>>(M);
    rownorm_kernel<<<(N * 32 + 255) / 256, 256>>>(emb, N, D, 0);
    rownorm_kernel<<<(C * 32 + 255) / 256, 256>>>(mmap, C, D, 1);
    if (out_ncell || out_ntime)
        copy_tables_kernel<<<(M + 255) / 256, 256>>>(node_cell, node_time,
                                                     out_ncell, out_ntime, M);
    winner_kernel<<<(N + 255) / 256, 256>>>(nodes, N, M);
    {
        dim3 grid(C / BN, (N + BM - 1) / BM);
        gemm_dist_tc<<<grid, 256>>>(emb, mmap, out_dist, N, C, D);
    }
    scatter_kernel<<<(N + 255) / 256, 256>>>(nodes, times, out_cells,
                                             out_ncell, out_ntime, N, M);
}

// round 9
// speedup vs baseline: 1.4059x; 1.1503x over previous
#include <cuda_runtime.h>
#include <cuda_bf16.h>
#include <math.h>
#include <stdint.h>

// Problem constants: N=100000, D=128, C=1024, NUM_NODES=1e6.
#define MAX_N     100000
#define MAX_NODES 1000000
#define NCB       8            // C / BN column blocks

// Device scratch (no allocs allowed). NO 64-bit atomics (sm_103a trap).
__device__ unsigned long long g_cand[(size_t)(MAX_N + 128) * NCB];
__device__ int   g_winner[MAX_NODES];
__device__ float g_rn[MAX_N];
__device__ float g_cn[2048];

// ---------------------------------------------------------------------------
__global__ void rownorm_kernel(const float* __restrict__ X, int n, int D, int is_col) {
    int warp = (blockIdx.x * blockDim.x + threadIdx.x) >> 5;
    int lane = threadIdx.x & 31;
    if (warp >= n) return;
    const float* row = X + (size_t)warp * D;
    float s = 0.f;
    for (int k = lane; k < D; k += 32) { float v = row[k]; s += v * v; }
    #pragma unroll
    for (int o = 16; o; o >>= 1) s += __shfl_xor_sync(0xFFFFFFFFu, s, o);
    if (lane == 0) { if (is_col) g_cn[warp] = s; else g_rn[warp] = s; }
}

// Fused: node-table copy + winner-table clear (same 1M index space).
__global__ void copy_clear_kernel(const int* __restrict__ node_cell,
                                  const float* __restrict__ node_time,
                                  float* __restrict__ out_ncell,
                                  float* __restrict__ out_ntime, int m) {
    int j = blockIdx.x * blockDim.x + threadIdx.x;
    if (j < m) {
        g_winner[j] = -1;
        if (out_ncell) out_ncell[j] = (float)node_cell[j];
        if (out_ntime) out_ntime[j] = node_time[j];
    }
}

__global__ void winner_kernel(const int* __restrict__ nodes, int n, int m) {
    int i = blockIdx.x * blockDim.x + threadIdx.x;
    if (i >= n) return;
    int nd = nodes[i];
    if (nd >= 0 && nd < m) atomicMax(&g_winner[nd], i);
}

// ---------------------------------------------------------------------------
// Tensor-core distance GEMM: 3xTF32 (hh + hl + lh) == fp32 accuracy.
// R5 inner loop (inline split at fragment load) + cp.async double buffering.
#define BM 128
#define BN 128
#define BK 32
#define SROW (BK + 4)          // 36-float row stride: 16B-aligned, conflict-free
#define TILEF (BM * SROW)      // floats per tile
#define SMEM_BYTES (4 * TILEF * 4 + BM * 4 * 8)   // 2 bufs x (As+Bs) + best_sh

__device__ __forceinline__ uint32_t smem_u32(const void* p) {
    return (uint32_t)__cvta_generic_to_shared(p);
}
__device__ __forceinline__ void cp16(uint32_t dst, const void* src) {
    asm volatile("cp.async.cg.shared.global [%0], [%1], 16;\n"
                 :: "r"(dst), "l"(src));
}
__device__ __forceinline__ void cp_commit() {
    asm volatile("cp.async.commit_group;\n");
}
template <int n>
__device__ __forceinline__ void cp_wait() {
    asm volatile("cp.async.wait_group %0;\n" :: "n"(n));
}

__device__ __forceinline__ void split_tf32(float x, uint32_t& hi, uint32_t& lo) {
    uint32_t xb = __float_as_uint(x);
    uint32_t h  = (xb + 0x1000u) & 0xFFFFE000u;   // round-to-nearest tf32
    hi = h;
    lo = __float_as_uint(x - __uint_as_float(h));
}

__device__ __forceinline__ void mma_tf32(float* c, const uint32_t* a, const uint32_t* b) {
    asm volatile(
        "mma.sync.aligned.m16n8k8.row.col.f32.tf32.tf32.f32 "
        "{%0,%1,%2,%3}, {%4,%5,%6,%7}, {%8,%9}, {%0,%1,%2,%3};\n"
        : "+f"(c[0]), "+f"(c[1]), "+f"(c[2]), "+f"(c[3])
        : "r"(a[0]), "r"(a[1]), "r"(a[2]), "r"(a[3]), "r"(b[0]), "r"(b[1]));
}

__global__ __launch_bounds__(256, 2)
void gemm_dist_tc(const float* __restrict__ A,   // [N, 128]
                  const float* __restrict__ B,   // [1024, 128]
                  float* __restrict__ out,       // [N, 1024] (may be null)
                  int N, int C, int D) {
    extern __shared__ float smem[];
    float* Asb[2] = { smem,             smem + 2 * TILEF };
    float* Bsb[2] = { smem + TILEF,     smem + 3 * TILEF };
    unsigned long long* best_sh = (unsigned long long*)(smem + 4 * TILEF);

    const int tid   = threadIdx.x;
    const int lane  = tid & 31;
    const int warp  = tid >> 5;
    const int warpM = warp >> 2;       // 0..1
    const int warpN = warp & 3;        // 0..3
    const int brow  = blockIdx.y * BM;
    const int bcol  = blockIdx.x * BN;
    const int g     = lane >> 2;       // groupID 0..7
    const int q     = lane & 3;        // quad lane 0..3

    float acc[4][4][4];                // [mtile][ntile][reg]
    #pragma unroll
    for (int mt = 0; mt < 4; mt++)
        #pragma unroll
        for (int nt = 0; nt < 4; nt++)
            #pragma unroll
            for (int r = 0; r < 4; r++) acc[mt][nt][r] = 0.f;

    // cp.async loader mapping: 256 threads; row = tid>>3 (+i*32), col4 = (tid&7)*4.
    const int lrow = tid >> 3;          // 0..31
    const int lk4  = (tid & 7) * 4;     // 0..28

    // issue loads for chunk kc into buffer b
    auto issue = [&](int kc, int b) {
        const int k0 = kc * BK;
        #pragma unroll
        for (int i = 0; i < 4; i++) {
            int row = lrow + i * 32;
            int ar = min(brow + row, N - 1);
            uint32_t doff = (uint32_t)(row * SROW + lk4) * 4u;
            cp16(smem_u32(Asb[b]) + doff, A + (size_t)ar * D + k0 + lk4);
            cp16(smem_u32(Bsb[b]) + doff, B + (size_t)(bcol + row) * D + k0 + lk4);
        }
        cp_commit();
    };

    issue(0, 0);

    for (int kc = 0; kc < 4; kc++) {
        const int buf = kc & 1;
        if (kc < 3) { issue(kc + 1, buf ^ 1); cp_wait<1>(); }
        else        { cp_wait<0>(); }
        __syncthreads();

        const float* As = Asb[buf];
        const float* Bs = Bsb[buf];
        #pragma unroll
        for (int kk = 0; kk < 4; kk++) {
            const int kb = kk * 8;
            const int c0 = kb + q;
            uint32_t ah[4][4], al[4][4];
            #pragma unroll
            for (int mt = 0; mt < 4; mt++) {
                int r0 = (warpM * 64 + mt * 16 + g) * SROW;
                split_tf32(As[r0 + c0],                ah[mt][0], al[mt][0]);
                split_tf32(As[r0 + 8 * SROW + c0],     ah[mt][1], al[mt][1]);
                split_tf32(As[r0 + c0 + 4],            ah[mt][2], al[mt][2]);
                split_tf32(As[r0 + 8 * SROW + c0 + 4], ah[mt][3], al[mt][3]);
            }
            #pragma unroll
            for (int nt = 0; nt < 4; nt++) {
                int n0 = (warpN * 32 + nt * 8 + g) * SROW;
                uint32_t bh[2], bl[2];
                split_tf32(Bs[n0 + c0],     bh[0], bl[0]);
                split_tf32(Bs[n0 + c0 + 4], bh[1], bl[1]);
                #pragma unroll
                for (int mt = 0; mt < 4; mt++) {
                    mma_tf32(acc[mt][nt], ah[mt], bh);
                    mma_tf32(acc[mt][nt], ah[mt], bl);
                    mma_tf32(acc[mt][nt], al[mt], bh);
                }
            }
        }
        if (kc < 3) __syncthreads();   // all reads of this buf done before reuse
    }

    // Epilogue: distances + per-row argmin keys.
    float cn0[4], cn1[4];
    #pragma unroll
    for (int nt = 0; nt < 4; nt++) {
        int col = bcol + warpN * 32 + nt * 8 + q * 2;
        cn0[nt] = g_cn[col];
        cn1[nt] = g_cn[col + 1];
    }

    #pragma unroll
    for (int mt = 0; mt < 4; mt++) {
        #pragma unroll
        for (int half = 0; half < 2; half++) {
            int rloc = warpM * 64 + mt * 16 + g + half * 8;
            int grow = brow + rloc;
            bool rowok = (grow < N);
            float rn = rowok ? g_rn[grow] : 0.f;
            unsigned long long best = ~0ull;
            #pragma unroll
            for (int nt = 0; nt < 4; nt++) {
                int col = bcol + warpN * 32 + nt * 8 + q * 2;
                float d0 = sqrtf(fmaxf(rn + cn0[nt] - 2.0f * acc[mt][nt][half * 2 + 0], 0.f));
                float d1 = sqrtf(fmaxf(rn + cn1[nt] - 2.0f * acc[mt][nt][half * 2 + 1], 0.f));
                unsigned long long k0 =
                    ((unsigned long long)__float_as_uint(d0) << 32) | (unsigned)col;
                unsigned long long k1 =
                    ((unsigned long long)__float_as_uint(d1) << 32) | (unsigned)(col + 1);
                best = (k0 < best) ? k0 : best;
                best = (k1 < best) ? k1 : best;
                if (rowok && out) {
                    float2 dv = make_float2(d0, d1);
                    *(float2*)(out + (size_t)grow * C + col) = dv;
                }
            }
            #pragma unroll
            for (int o = 1; o <= 2; o <<= 1) {
                unsigned long long other = __shfl_xor_sync(0xFFFFFFFFu, best, o);
                best = (other < best) ? other : best;
            }
            if (q == 0) best_sh[rloc * 4 + warpN] = best;
        }
    }
    __syncthreads();

    if (tid < BM) {
        int grow = brow + tid;
        if (grow < N) {
            unsigned long long best = best_sh[tid * 4];
            #pragma unroll
            for (int j = 1; j < 4; j++) {
                unsigned long long k = best_sh[tid * 4 + j];
                best = (k < best) ? k : best;
            }
            g_cand[(size_t)grow * NCB + blockIdx.x] = best;
        }
    }
}

// ---------------------------------------------------------------------------
__global__ void scatter_kernel(const int* __restrict__ nodes,
                               const float* __restrict__ times,
                               float* __restrict__ out_cells,
                               float* __restrict__ out_ncell,
                               float* __restrict__ out_ntime, int n, int m) {
    int i = blockIdx.x * blockDim.x + threadIdx.x;
    if (i >= n) return;
    const unsigned long long* cand = &g_cand[(size_t)i * NCB];
    unsigned long long best = cand[0];
    #pragma unroll
    for (int cb = 1; cb < NCB; cb++) {
        unsigned long long k = cand[cb];
        best = (k < best) ? k : best;
    }
    int cell = (int)(unsigned)(best & 0xFFFFFFFFull);
    if (out_cells) out_cells[i] = (float)cell;
    int nd = nodes[i];
    if (nd >= 0 && nd < m && g_winner[nd] == i) {
        if (out_ncell) out_ncell[nd] = (float)cell;
        if (out_ntime) out_ntime[nd] = times[i];
    }
}

// ---------------------------------------------------------------------------
extern "C" void kernel_launch(void* const* d_in, const int* in_sizes, int n_in,
                              void* d_out, int out_size) {
    const float* emb       = (const float*)d_in[0];   // [N, D]
    const float* mmap      = (const float*)d_in[1];   // [C, D]
    const int*   nodes     = (const int*)d_in[2];     // [N]
    const float* times     = (const float*)d_in[3];   // [N]
    const int*   node_cell = (const int*)d_in[4];     // [NUM_NODES]
    const float* node_time = (const float*)d_in[5];   // [NUM_NODES]

    const int D = 128;
    const int N = in_sizes[0] / D;       // 100000
    const int C = in_sizes[1] / D;       // 1024
    const int M = in_sizes[4];           // 1000000

    size_t have = (size_t)out_size;
    size_t nc = (size_t)N * C;
    float* base = (float*)d_out;
    float* out_dist  = (have >= nc) ? base : nullptr;
    float* out_cells = (have >= nc + (size_t)N) ? base + nc : nullptr;
    float* out_ncell = (have >= nc + N + (size_t)M) ? base + nc + N : nullptr;
    float* out_ntime = (have >= nc + N + 2ull * M) ? base + nc + N + M : nullptr;

    rownorm_kernel<<<(N * 32 + 255) / 256, 256>>>(emb, N, D, 0);
    rownorm_kernel<<<(C * 32 + 255) / 256, 256>>>(mmap, C, D, 1);
    copy_clear_kernel<<<(M + 255) / 256, 256>>>(node_cell, node_time,
                                                out_ncell, out_ntime, M);
    winner_kernel<<<(N + 255) / 256, 256>>>(nodes, N, M);
    {
        cudaFuncSetAttribute(gemm_dist_tc,
                             cudaFuncAttributeMaxDynamicSharedMemorySize, SMEM_BYTES);
        dim3 grid(C / BN, (N + BM - 1) / BM);
        gemm_dist_tc<<<grid, 256, SMEM_BYTES>>>(emb, mmap, out_dist, N, C, D);
    }
    scatter_kernel<<<(N + 255) / 256, 256>>>(nodes, times, out_cells,
                                             out_ncell, out_ntime, N, M);
}